// round 12
// baseline (speedup 1.0000x reference)
#include <cuda_runtime.h>
#include <cuda_fp16.h>
#include <mma.h>
#include <cstdint>

using namespace nvcuda;

#define NN 100000
#define NN_PAD 100096   // 782 * 128
#define MAXE 3300000
#define SCAN_BS 512

// ---------------- scratch (static device globals; zero-initialized) ---------
__device__ __align__(256) int    g_indeg[NN];
__device__ __align__(256) int    g_outdeg[NN];
__device__ __align__(256) int    g_fill[NN];
__device__ __align__(256) int    g_rowptr[NN + 1];
__device__ __align__(256) int    g_blocksums[256];
__device__ __align__(256) int    g_esrc[MAXE];
__device__ __align__(256) float  g_snorm[NN];
__device__ __align__(256) float  g_dnorm[NN];
__device__ __align__(256) __half g_xh[(size_t)NN_PAD * 256];    // feat fp16 / L1 out
__device__ __align__(256) __half g_aggh[(size_t)NN_PAD * 256];  // agg fp16
__device__ __align__(256) __half g_hh[(size_t)NN_PAD * 256];    // L0 out
__device__ __align__(256) __half g_xmh[(size_t)NN_PAD * 64];    // xm fp16
__device__ __align__(256) __half g_w0h[256 * 256];
__device__ __align__(256) __half g_w1h[256 * 256];
__device__ __align__(256) __half g_w2h[256 * 64];

// ---------------- degrees --------------------------------------------------
__global__ void zero_init_kernel() {
    int i = blockIdx.x * blockDim.x + threadIdx.x;
    if (i < NN) { g_indeg[i] = 0; g_outdeg[i] = 0; }
}

__global__ void degree_kernel(const int* __restrict__ src,
                              const int* __restrict__ dst, int nE) {
    int i = blockIdx.x * blockDim.x + threadIdx.x;
    if (i < nE) {
        atomicAdd(&g_outdeg[src[i]], 1);
        atomicAdd(&g_indeg[dst[i]], 1);
    }
}

// ---------------- CSR build (norms fused into scan3) -------------------------
__global__ void scan1_kernel() {
    __shared__ int sh[SCAN_BS];
    int i = blockIdx.x * SCAN_BS + threadIdx.x;
    int v = (i < NN) ? g_indeg[i] : 0;
    sh[threadIdx.x] = v;
    __syncthreads();
    for (int off = 1; off < SCAN_BS; off <<= 1) {
        int t = (threadIdx.x >= off) ? sh[threadIdx.x - off] : 0;
        __syncthreads();
        sh[threadIdx.x] += t;
        __syncthreads();
    }
    if (i < NN) g_rowptr[i] = sh[threadIdx.x] - v;
    if (threadIdx.x == SCAN_BS - 1) g_blocksums[blockIdx.x] = sh[threadIdx.x];
}

__global__ void scan2_kernel(int nb) {
    __shared__ int sh[256];
    int t = threadIdx.x;
    int v = (t < nb) ? g_blocksums[t] : 0;
    sh[t] = v;
    __syncthreads();
    for (int off = 1; off < 256; off <<= 1) {
        int u = (t >= off) ? sh[t - off] : 0;
        __syncthreads();
        sh[t] += u;
        __syncthreads();
    }
    if (t < nb) g_blocksums[t] = sh[t] - v;
}

__global__ void scan3_kernel(int nE) {
    int i = blockIdx.x * SCAN_BS + threadIdx.x;
    if (i < NN) {
        int rp = g_rowptr[i] + g_blocksums[blockIdx.x];
        g_rowptr[i] = rp;
        g_fill[i] = rp;
        g_snorm[i] = rsqrtf(fmaxf((float)g_outdeg[i], 1.f));
        g_dnorm[i] = rsqrtf(fmaxf((float)g_indeg[i], 1.f));
    }
    if (i == 0) g_rowptr[NN] = nE;
}

__global__ void fillcsr_kernel(const int* __restrict__ src,
                               const int* __restrict__ dst, int nE) {
    int i = blockIdx.x * blockDim.x + threadIdx.x;
    if (i < nE) {
        int pos = atomicAdd(&g_fill[dst[i]], 1);
        g_esrc[pos] = src[i];
    }
}

// ---------------- fp32 -> fp16 converts --------------------------------------
__global__ void convert_half_kernel(const float* __restrict__ in,
                                    __half* __restrict__ out, int n8) {
    int i = blockIdx.x * blockDim.x + threadIdx.x;
    if (i >= n8) return;
    float4 a = ((const float4*)in)[i * 2];
    float4 b = ((const float4*)in)[i * 2 + 1];
    __half2 h[4];
    h[0] = __floats2half2_rn(a.x, a.y);
    h[1] = __floats2half2_rn(a.z, a.w);
    h[2] = __floats2half2_rn(b.x, b.y);
    h[3] = __floats2half2_rn(b.z, b.w);
    ((uint4*)out)[i] = *(const uint4*)h;
}

// all three weights in one launch. W0:[0,8192) W1:[8192,16384) W2:[16384,18432)
__global__ void convert_weights_kernel(const float* __restrict__ W0,
                                       const float* __restrict__ W1,
                                       const float* __restrict__ W2) {
    int i = blockIdx.x * blockDim.x + threadIdx.x;
    const float* in;
    __half* out;
    int off;
    if (i < 8192) { in = W0; out = g_w0h; off = i; }
    else if (i < 16384) { in = W1; out = g_w1h; off = i - 8192; }
    else if (i < 18432) { in = W2; out = g_w2h; off = i - 16384; }
    else return;
    float4 a = ((const float4*)in)[off * 2];
    float4 b = ((const float4*)in)[off * 2 + 1];
    __half2 h[4];
    h[0] = __floats2half2_rn(a.x, a.y);
    h[1] = __floats2half2_rn(a.z, a.w);
    h[2] = __floats2half2_rn(b.x, b.y);
    h[3] = __floats2half2_rn(b.z, b.w);
    ((uint4*)out)[off] = *(const uint4*)h;
}

// ---------------- gather256: fp16 in, fp32 accum, fp16 out -------------------
// processes dst nodes in [v0, v1)
__global__ __launch_bounds__(256) void gather256h_kernel(
    const __half* __restrict__ x, __half* __restrict__ out, int v0, int v1) {
    int v = v0 + ((blockIdx.x * blockDim.x + threadIdx.x) >> 5);
    int lane = threadIdx.x & 31;
    if (v >= v1) return;
    int row = g_rowptr[v];
    int end = g_rowptr[v + 1];
    float acc[8] = {0.f, 0.f, 0.f, 0.f, 0.f, 0.f, 0.f, 0.f};

    for (int base = row; base < end; base += 32) {
        int n = min(32, end - base);
        int s = 0;
        float w = 0.f;
        if (lane < n) { s = __ldg(&g_esrc[base + lane]); w = __ldg(&g_snorm[s]); }
        int k = 0;
        for (; k + 4 <= n; k += 4) {
            int s0 = __shfl_sync(0xffffffffu, s, k);
            int s1 = __shfl_sync(0xffffffffu, s, k + 1);
            int s2 = __shfl_sync(0xffffffffu, s, k + 2);
            int s3 = __shfl_sync(0xffffffffu, s, k + 3);
            float w0 = __shfl_sync(0xffffffffu, w, k);
            float w1 = __shfl_sync(0xffffffffu, w, k + 1);
            float w2 = __shfl_sync(0xffffffffu, w, k + 2);
            float w3 = __shfl_sync(0xffffffffu, w, k + 3);
            uint4 u0 = __ldg((const uint4*)(x + (size_t)s0 * 256) + lane);
            uint4 u1 = __ldg((const uint4*)(x + (size_t)s1 * 256) + lane);
            uint4 u2 = __ldg((const uint4*)(x + (size_t)s2 * 256) + lane);
            uint4 u3 = __ldg((const uint4*)(x + (size_t)s3 * 256) + lane);
            const __half2* p0 = (const __half2*)&u0;
            const __half2* p1 = (const __half2*)&u1;
            const __half2* p2 = (const __half2*)&u2;
            const __half2* p3 = (const __half2*)&u3;
#pragma unroll
            for (int j = 0; j < 4; j++) {
                float2 f0 = __half22float2(p0[j]);
                float2 f1 = __half22float2(p1[j]);
                float2 f2 = __half22float2(p2[j]);
                float2 f3 = __half22float2(p3[j]);
                acc[j * 2 + 0] += (w0 * f0.x + w1 * f1.x) + (w2 * f2.x + w3 * f3.x);
                acc[j * 2 + 1] += (w0 * f0.y + w1 * f1.y) + (w2 * f2.y + w3 * f3.y);
            }
        }
        for (; k < n; k++) {
            int s0 = __shfl_sync(0xffffffffu, s, k);
            float w0 = __shfl_sync(0xffffffffu, w, k);
            uint4 u0 = __ldg((const uint4*)(x + (size_t)s0 * 256) + lane);
            const __half2* p0 = (const __half2*)&u0;
#pragma unroll
            for (int j = 0; j < 4; j++) {
                float2 f0 = __half22float2(p0[j]);
                acc[j * 2 + 0] += w0 * f0.x;
                acc[j * 2 + 1] += w0 * f0.y;
            }
        }
    }
    __half2 hv[4];
#pragma unroll
    for (int j = 0; j < 4; j++)
        hv[j] = __floats2half2_rn(acc[j * 2], acc[j * 2 + 1]);
    ((uint4*)(out + (size_t)v * 256))[lane] = *(const uint4*)hv;
}

// ---------------- gather64: fp16 in, fp32 out --------------------------------
__global__ __launch_bounds__(256) void gather64h_kernel(
    const __half* __restrict__ x, float* __restrict__ out) {
    int v = (blockIdx.x * blockDim.x + threadIdx.x) >> 5;
    int lane = threadIdx.x & 31;
    if (v >= NN) return;
    int row = g_rowptr[v];
    int end = g_rowptr[v + 1];
    float2 acc = make_float2(0.f, 0.f);
    for (int base = row; base < end; base += 32) {
        int n = min(32, end - base);
        int s = 0;
        if (lane < n) s = __ldg(&g_esrc[base + lane]);
        int k = 0;
        for (; k + 4 <= n; k += 4) {
            int s0 = __shfl_sync(0xffffffffu, s, k);
            int s1 = __shfl_sync(0xffffffffu, s, k + 1);
            int s2 = __shfl_sync(0xffffffffu, s, k + 2);
            int s3 = __shfl_sync(0xffffffffu, s, k + 3);
            __half2 a0 = __ldg((const __half2*)(x + (size_t)s0 * 64) + lane);
            __half2 a1 = __ldg((const __half2*)(x + (size_t)s1 * 64) + lane);
            __half2 a2 = __ldg((const __half2*)(x + (size_t)s2 * 64) + lane);
            __half2 a3 = __ldg((const __half2*)(x + (size_t)s3 * 64) + lane);
            float2 f0 = __half22float2(a0);
            float2 f1 = __half22float2(a1);
            float2 f2 = __half22float2(a2);
            float2 f3 = __half22float2(a3);
            acc.x += (f0.x + f1.x) + (f2.x + f3.x);
            acc.y += (f0.y + f1.y) + (f2.y + f3.y);
        }
        for (; k < n; k++) {
            int s0 = __shfl_sync(0xffffffffu, s, k);
            float2 f0 = __half22float2(__ldg((const __half2*)(x + (size_t)s0 * 64) + lane));
            acc.x += f0.x;
            acc.y += f0.y;
        }
    }
    float w = g_dnorm[v];
    ((float2*)(out + (size_t)v * 64))[lane] = make_float2(acc.x * w, acc.y * w);
}

// ---------------- fp16 tensor-core GEMM, BK=64, chunked rows -----------------
template <int BN, bool RELU>
__global__ __launch_bounds__(256, 2) void gemm_h_kernel(
    const __half* __restrict__ A, const __half* __restrict__ Wh,
    const float* __restrict__ norm, __half* __restrict__ C, int M, int N,
    int row_base_blocks) {
    constexpr int BM = 128, BK = 64;
    constexpr int WM = (BN == 128) ? 64 : 32;
    constexpr int FM = WM / 16;
    constexpr int BQ = (BN == 128) ? 4 : 2;
    __shared__ __half As[BM][BK + 8];
    __shared__ __half Bs[BK][BN + 8];
    __shared__ float  stage[8][16 * 24];

    const int t = threadIdx.x;
    const int warp = t >> 5;
    const int lane = t & 31;
    const int wm = (BN == 128) ? (warp >> 2) : (warp >> 1);
    const int wn = (BN == 128) ? (warp & 3) : (warp & 1);
    const int row0 = (row_base_blocks + blockIdx.x) * BM;
    const int col0 = blockIdx.y * BN;

    const int a_row = t >> 1;
    const int a_c0 = (t & 1) * 32;
    const bool a_ok = (row0 + a_row) < M;
    const float nrmf = a_ok ? __ldg(&norm[row0 + a_row]) : 0.f;
    const __half2 nrm2 = __float2half2_rn(nrmf);
    const __half* Aptr = A + (size_t)(row0 + a_row) * 256 + a_c0;

    const int b_row = t >> 2;
    const int b_c0 = (t & 3) * 8 * BQ;

    wmma::fragment<wmma::accumulator, 16, 16, 16, float> acc[FM][2];
#pragma unroll
    for (int i = 0; i < FM; i++)
#pragma unroll
        for (int j = 0; j < 2; j++) wmma::fill_fragment(acc[i][j], 0.f);

    uint4 ar[4], br[BQ];
#pragma unroll
    for (int q = 0; q < 4; q++) ar[q] = *(const uint4*)(Aptr + q * 8);
#pragma unroll
    for (int q = 0; q < BQ; q++)
        br[q] = *(const uint4*)&Wh[(size_t)b_row * N + col0 + b_c0 + q * 8];

    auto store_tiles = [&]() {
#pragma unroll
        for (int q = 0; q < 4; q++) {
            const __half2* p = (const __half2*)&ar[q];
            __half2* dstp = (__half2*)&As[a_row][a_c0 + q * 8];
#pragma unroll
            for (int j = 0; j < 4; j++) dstp[j] = __hmul2(p[j], nrm2);
        }
#pragma unroll
        for (int q = 0; q < BQ; q++)
            *(uint4*)&Bs[b_row][b_c0 + q * 8] = br[q];
    };

    store_tiles();
    __syncthreads();

    for (int k0 = 0; k0 < 256; k0 += BK) {
        const bool has_next = (k0 + BK) < 256;
        if (has_next) {
#pragma unroll
            for (int q = 0; q < 4; q++)
                ar[q] = *(const uint4*)(Aptr + k0 + BK + q * 8);
#pragma unroll
            for (int q = 0; q < BQ; q++)
                br[q] = *(const uint4*)&Wh[(size_t)(k0 + BK + b_row) * N + col0 + b_c0 + q * 8];
        }
#pragma unroll
        for (int kk = 0; kk < BK; kk += 16) {
            wmma::fragment<wmma::matrix_a, 16, 16, 16, __half, wmma::row_major> af[FM];
            wmma::fragment<wmma::matrix_b, 16, 16, 16, __half, wmma::row_major> bf[2];
#pragma unroll
            for (int i = 0; i < FM; i++)
                wmma::load_matrix_sync(af[i], &As[wm * WM + i * 16][kk], BK + 8);
#pragma unroll
            for (int j = 0; j < 2; j++)
                wmma::load_matrix_sync(bf[j], &Bs[kk][wn * 32 + j * 16], BN + 8);
#pragma unroll
            for (int i = 0; i < FM; i++)
#pragma unroll
                for (int j = 0; j < 2; j++)
                    wmma::mma_sync(acc[i][j], af[i], bf[j], acc[i][j]);
        }
        __syncthreads();
        if (has_next) {
            store_tiles();
            __syncthreads();
        }
    }

#pragma unroll
    for (int i = 0; i < FM; i++)
#pragma unroll
        for (int j = 0; j < 2; j++) {
            if (RELU) {
#pragma unroll
                for (int e = 0; e < acc[i][j].num_elements; e++)
                    acc[i][j].x[e] = fmaxf(acc[i][j].x[e], 0.f);
            }
            wmma::store_matrix_sync(&stage[warp][0], acc[i][j], 24,
                                    wmma::mem_row_major);
            __syncwarp();
            int r = lane >> 1;
            int ch = (lane & 1) * 8;
            const float* sp = &stage[warp][r * 24 + ch];
            __half2 hv[4];
#pragma unroll
            for (int q = 0; q < 4; q++)
                hv[q] = __floats2half2_rn(sp[q * 2], sp[q * 2 + 1]);
            __half* cp = C + (size_t)(row0 + wm * WM + i * 16 + r) * N +
                         col0 + wn * 32 + j * 16 + ch;
            *(uint4*)cp = *(const uint4*)hv;
            __syncwarp();
        }
}

// ---------------- launch -----------------------------------------------------
extern "C" void kernel_launch(void* const* d_in, const int* in_sizes, int n_in,
                              void* d_out, int out_size) {
    const float* feat = (const float*)d_in[0];
    const int* src = (const int*)d_in[1];
    const int* dst = (const int*)d_in[2];
    const float* W0 = (const float*)d_in[3];
    const float* W1 = (const float*)d_in[4];
    const float* W2 = (const float*)d_in[5];
    float* out = (float*)d_out;
    const int nE = in_sizes[1];

    __half *xh, *aggh, *hh, *xmh, *w0h, *w1h, *w2h;
    float *snorm, *dnorm;
    cudaGetSymbolAddress((void**)&xh, g_xh);
    cudaGetSymbolAddress((void**)&aggh, g_aggh);
    cudaGetSymbolAddress((void**)&hh, g_hh);
    cudaGetSymbolAddress((void**)&xmh, g_xmh);
    cudaGetSymbolAddress((void**)&w0h, g_w0h);
    cudaGetSymbolAddress((void**)&w1h, g_w1h);
    cudaGetSymbolAddress((void**)&w2h, g_w2h);
    cudaGetSymbolAddress((void**)&snorm, g_snorm);
    cudaGetSymbolAddress((void**)&dnorm, g_dnorm);

    const int T = 256;
    const int NB = (NN + SCAN_BS - 1) / SCAN_BS;      // 196
    const int gemm_rows = NN_PAD / 128;               // 782
    const int gather_blocks = (NN * 32 + T - 1) / T;  // 12500
    const int conv8 = NN * 256 / 8;

    // chunking for layers 0/1: 4 row chunks (in units of 128-row GEMM blocks)
    const int NCH = 4;
    const int chb[NCH + 1] = {0, 196, 392, 587, 782};   // block boundaries

    // host-side stream/event resources (created once; no device memory)
    static cudaStream_t s_side = nullptr;
    static cudaEvent_t ev_fork = nullptr, ev_cjoin = nullptr;
    static cudaEvent_t ev_g[2][NCH];
    static cudaEvent_t ev_layer[2];
    if (s_side == nullptr) {
        if (cudaStreamCreateWithFlags(&s_side, cudaStreamNonBlocking) != cudaSuccess)
            s_side = nullptr;
        cudaEventCreateWithFlags(&ev_fork, cudaEventDisableTiming);
        cudaEventCreateWithFlags(&ev_cjoin, cudaEventDisableTiming);
        for (int l = 0; l < 2; l++) {
            cudaEventCreateWithFlags(&ev_layer[l], cudaEventDisableTiming);
            for (int c = 0; c < NCH; c++)
                cudaEventCreateWithFlags(&ev_g[l][c], cudaEventDisableTiming);
        }
    }
    const bool dual = (s_side != nullptr);

    // ---- converts (side) ∥ CSR build (main) ---------------------------------
    if (dual) {
        cudaEventRecord(ev_fork, 0);
        cudaStreamWaitEvent(s_side, ev_fork, 0);
        convert_half_kernel<<<(conv8 + T - 1) / T, T, 0, s_side>>>(feat, xh, conv8);
        convert_weights_kernel<<<(18432 + T - 1) / T, T, 0, s_side>>>(W0, W1, W2);
        cudaEventRecord(ev_cjoin, s_side);
    } else {
        convert_half_kernel<<<(conv8 + T - 1) / T, T>>>(feat, xh, conv8);
        convert_weights_kernel<<<(18432 + T - 1) / T, T>>>(W0, W1, W2);
    }

    zero_init_kernel<<<(NN + T - 1) / T, T>>>();
    degree_kernel<<<(nE + T - 1) / T, T>>>(src, dst, nE);
    scan1_kernel<<<NB, SCAN_BS>>>();
    scan2_kernel<<<1, 256>>>(NB);
    scan3_kernel<<<NB, SCAN_BS>>>(nE);
    fillcsr_kernel<<<(nE + T - 1) / T, T>>>(src, dst, nE);
    if (dual) cudaStreamWaitEvent(0, ev_cjoin, 0);

    // ---- layers 0 and 1: chunked gather (main) ∥ GEMM (side) ----------------
    // Ping-pong: L0 reads xh, writes hh.  L1 reads hh, writes xh.  No aliasing
    // between a layer's concurrent gather (reads input everywhere) and its
    // GEMM (writes output chunks).
    const __half* lay_in[2] = {xh, hh};
    __half* lay_out[2] = {hh, xh};
    const __half* lay_w[2] = {w0h, w1h};
    for (int l = 0; l < 2; l++) {
        if (dual) {
            for (int c = 0; c < NCH; c++) {
                int v0 = chb[c] * 128;
                int v1 = min(chb[c + 1] * 128, NN);
                int nwarp = v1 - v0;
                gather256h_kernel<<<(nwarp * 32 + T - 1) / T, T>>>(lay_in[l], aggh, v0, v1);
                cudaEventRecord(ev_g[l][c], 0);
            }
            for (int c = 0; c < NCH; c++) {
                cudaStreamWaitEvent(s_side, ev_g[l][c], 0);
                gemm_h_kernel<128, true><<<dim3(chb[c + 1] - chb[c], 2), T, 0, s_side>>>(
                    aggh, lay_w[l], dnorm, lay_out[l], NN, 256, chb[c]);
            }
            cudaEventRecord(ev_layer[l], s_side);
            cudaStreamWaitEvent(0, ev_layer[l], 0);
        } else {
            gather256h_kernel<<<gather_blocks, T>>>(lay_in[l], aggh, 0, NN);
            gemm_h_kernel<128, true><<<dim3(gemm_rows, 2), T>>>(
                aggh, lay_w[l], dnorm, lay_out[l], NN, 256, 0);
        }
    }

    // ---- layer 2: xmh = (xh * snorm) @ W2; out = dnorm * (A^T xmh) ----------
    gemm_h_kernel<64, false><<<dim3(gemm_rows, 1), T>>>(xh, w2h, snorm, xmh, NN, 64, 0);
    gather64h_kernel<<<gather_blocks, T>>>(xmh, out);
}

// round 13
// speedup vs baseline: 1.0391x; 1.0391x over previous
#include <cuda_runtime.h>
#include <cuda_fp16.h>
#include <mma.h>
#include <cstdint>

using namespace nvcuda;

#define NN 100000
#define NN_PAD 100096   // 782 * 128
#define MAXE 3300000
#define SCAN_BS 512

// ---------------- scratch (static device globals; zero-initialized) ---------
__device__ __align__(256) int    g_indeg[NN];
__device__ __align__(256) int    g_outdeg[NN];
__device__ __align__(256) int    g_fill[NN];
__device__ __align__(256) int    g_rowptr[NN + 1];
__device__ __align__(256) int    g_blocksums[256];
__device__ __align__(256) int    g_esrc[MAXE];
__device__ __align__(256) float  g_snorm[NN];
__device__ __align__(256) float  g_dnorm[NN];
__device__ __align__(256) __half g_xh[(size_t)NN_PAD * 256];    // feat fp16
__device__ __align__(256) __half g_aggh[(size_t)NN_PAD * 256];  // agg fp16
__device__ __align__(256) __half g_hh[(size_t)NN_PAD * 256];    // h fp16
__device__ __align__(256) __half g_xmh[(size_t)NN_PAD * 64];    // xm fp16
__device__ __align__(256) __half g_w0h[256 * 256];
__device__ __align__(256) __half g_w1h[256 * 256];
__device__ __align__(256) __half g_w2h[256 * 64];

// ---------------- degrees --------------------------------------------------
__global__ void zero_init_kernel() {
    int i = blockIdx.x * blockDim.x + threadIdx.x;
    if (i < NN) { g_indeg[i] = 0; g_outdeg[i] = 0; }
}

// 4 edges per thread via int4 loads
__global__ void degree_kernel(const int* __restrict__ src,
                              const int* __restrict__ dst, int nE) {
    int i = blockIdx.x * blockDim.x + threadIdx.x;
    int base = i * 4;
    if (base + 4 <= nE) {
        int4 s = *(const int4*)(src + base);
        int4 d = *(const int4*)(dst + base);
        atomicAdd(&g_outdeg[s.x], 1);
        atomicAdd(&g_outdeg[s.y], 1);
        atomicAdd(&g_outdeg[s.z], 1);
        atomicAdd(&g_outdeg[s.w], 1);
        atomicAdd(&g_indeg[d.x], 1);
        atomicAdd(&g_indeg[d.y], 1);
        atomicAdd(&g_indeg[d.z], 1);
        atomicAdd(&g_indeg[d.w], 1);
    } else {
        for (int e = base; e < nE; e++) {
            atomicAdd(&g_outdeg[src[e]], 1);
            atomicAdd(&g_indeg[dst[e]], 1);
        }
    }
}

// ---------------- CSR build (norms fused into scan3) -------------------------
__global__ void scan1_kernel() {
    __shared__ int sh[SCAN_BS];
    int i = blockIdx.x * SCAN_BS + threadIdx.x;
    int v = (i < NN) ? g_indeg[i] : 0;
    sh[threadIdx.x] = v;
    __syncthreads();
    for (int off = 1; off < SCAN_BS; off <<= 1) {
        int t = (threadIdx.x >= off) ? sh[threadIdx.x - off] : 0;
        __syncthreads();
        sh[threadIdx.x] += t;
        __syncthreads();
    }
    if (i < NN) g_rowptr[i] = sh[threadIdx.x] - v;
    if (threadIdx.x == SCAN_BS - 1) g_blocksums[blockIdx.x] = sh[threadIdx.x];
}

__global__ void scan2_kernel(int nb) {
    __shared__ int sh[256];
    int t = threadIdx.x;
    int v = (t < nb) ? g_blocksums[t] : 0;
    sh[t] = v;
    __syncthreads();
    for (int off = 1; off < 256; off <<= 1) {
        int u = (t >= off) ? sh[t - off] : 0;
        __syncthreads();
        sh[t] += u;
        __syncthreads();
    }
    if (t < nb) g_blocksums[t] = sh[t] - v;
}

__global__ void scan3_kernel(int nE) {
    int i = blockIdx.x * SCAN_BS + threadIdx.x;
    if (i < NN) {
        int rp = g_rowptr[i] + g_blocksums[blockIdx.x];
        g_rowptr[i] = rp;
        g_fill[i] = rp;
        g_snorm[i] = rsqrtf(fmaxf((float)g_outdeg[i], 1.f));
        g_dnorm[i] = rsqrtf(fmaxf((float)g_indeg[i], 1.f));
    }
    if (i == 0) g_rowptr[NN] = nE;
}

// 4 edges per thread via int4 loads
__global__ void fillcsr_kernel(const int* __restrict__ src,
                               const int* __restrict__ dst, int nE) {
    int i = blockIdx.x * blockDim.x + threadIdx.x;
    int base = i * 4;
    if (base + 4 <= nE) {
        int4 s = *(const int4*)(src + base);
        int4 d = *(const int4*)(dst + base);
        g_esrc[atomicAdd(&g_fill[d.x], 1)] = s.x;
        g_esrc[atomicAdd(&g_fill[d.y], 1)] = s.y;
        g_esrc[atomicAdd(&g_fill[d.z], 1)] = s.z;
        g_esrc[atomicAdd(&g_fill[d.w], 1)] = s.w;
    } else {
        for (int e = base; e < nE; e++)
            g_esrc[atomicAdd(&g_fill[dst[e]], 1)] = src[e];
    }
}

// ---------------- fp32 -> fp16 converts --------------------------------------
__global__ void convert_half_kernel(const float* __restrict__ in,
                                    __half* __restrict__ out, int n8) {
    int i = blockIdx.x * blockDim.x + threadIdx.x;
    if (i >= n8) return;
    float4 a = ((const float4*)in)[i * 2];
    float4 b = ((const float4*)in)[i * 2 + 1];
    __half2 h[4];
    h[0] = __floats2half2_rn(a.x, a.y);
    h[1] = __floats2half2_rn(a.z, a.w);
    h[2] = __floats2half2_rn(b.x, b.y);
    h[3] = __floats2half2_rn(b.z, b.w);
    ((uint4*)out)[i] = *(const uint4*)h;
}

// all three weights in one launch. W0:[0,8192) W1:[8192,16384) W2:[16384,18432)
__global__ void convert_weights_kernel(const float* __restrict__ W0,
                                       const float* __restrict__ W1,
                                       const float* __restrict__ W2) {
    int i = blockIdx.x * blockDim.x + threadIdx.x;
    const float* in;
    __half* out;
    int off;
    if (i < 8192) { in = W0; out = g_w0h; off = i; }
    else if (i < 16384) { in = W1; out = g_w1h; off = i - 8192; }
    else if (i < 18432) { in = W2; out = g_w2h; off = i - 16384; }
    else return;
    float4 a = ((const float4*)in)[off * 2];
    float4 b = ((const float4*)in)[off * 2 + 1];
    __half2 h[4];
    h[0] = __floats2half2_rn(a.x, a.y);
    h[1] = __floats2half2_rn(a.z, a.w);
    h[2] = __floats2half2_rn(b.x, b.y);
    h[3] = __floats2half2_rn(b.z, b.w);
    ((uint4*)out)[off] = *(const uint4*)h;
}

// ---------------- gather256: fp16 in, fp32 accum, fp16 out -------------------
__global__ __launch_bounds__(256) void gather256h_kernel(
    const __half* __restrict__ x, __half* __restrict__ out) {
    int v = (blockIdx.x * blockDim.x + threadIdx.x) >> 5;
    int lane = threadIdx.x & 31;
    if (v >= NN) return;
    int row = g_rowptr[v];
    int end = g_rowptr[v + 1];
    float acc[8] = {0.f, 0.f, 0.f, 0.f, 0.f, 0.f, 0.f, 0.f};

    for (int base = row; base < end; base += 32) {
        int n = min(32, end - base);
        int s = 0;
        float w = 0.f;
        if (lane < n) { s = __ldg(&g_esrc[base + lane]); w = __ldg(&g_snorm[s]); }
        int k = 0;
        for (; k + 4 <= n; k += 4) {
            int s0 = __shfl_sync(0xffffffffu, s, k);
            int s1 = __shfl_sync(0xffffffffu, s, k + 1);
            int s2 = __shfl_sync(0xffffffffu, s, k + 2);
            int s3 = __shfl_sync(0xffffffffu, s, k + 3);
            float w0 = __shfl_sync(0xffffffffu, w, k);
            float w1 = __shfl_sync(0xffffffffu, w, k + 1);
            float w2 = __shfl_sync(0xffffffffu, w, k + 2);
            float w3 = __shfl_sync(0xffffffffu, w, k + 3);
            uint4 u0 = __ldg((const uint4*)(x + (size_t)s0 * 256) + lane);
            uint4 u1 = __ldg((const uint4*)(x + (size_t)s1 * 256) + lane);
            uint4 u2 = __ldg((const uint4*)(x + (size_t)s2 * 256) + lane);
            uint4 u3 = __ldg((const uint4*)(x + (size_t)s3 * 256) + lane);
            const __half2* p0 = (const __half2*)&u0;
            const __half2* p1 = (const __half2*)&u1;
            const __half2* p2 = (const __half2*)&u2;
            const __half2* p3 = (const __half2*)&u3;
#pragma unroll
            for (int j = 0; j < 4; j++) {
                float2 f0 = __half22float2(p0[j]);
                float2 f1 = __half22float2(p1[j]);
                float2 f2 = __half22float2(p2[j]);
                float2 f3 = __half22float2(p3[j]);
                acc[j * 2 + 0] += (w0 * f0.x + w1 * f1.x) + (w2 * f2.x + w3 * f3.x);
                acc[j * 2 + 1] += (w0 * f0.y + w1 * f1.y) + (w2 * f2.y + w3 * f3.y);
            }
        }
        for (; k < n; k++) {
            int s0 = __shfl_sync(0xffffffffu, s, k);
            float w0 = __shfl_sync(0xffffffffu, w, k);
            uint4 u0 = __ldg((const uint4*)(x + (size_t)s0 * 256) + lane);
            const __half2* p0 = (const __half2*)&u0;
#pragma unroll
            for (int j = 0; j < 4; j++) {
                float2 f0 = __half22float2(p0[j]);
                acc[j * 2 + 0] += w0 * f0.x;
                acc[j * 2 + 1] += w0 * f0.y;
            }
        }
    }
    __half2 hv[4];
#pragma unroll
    for (int j = 0; j < 4; j++)
        hv[j] = __floats2half2_rn(acc[j * 2], acc[j * 2 + 1]);
    ((uint4*)(out + (size_t)v * 256))[lane] = *(const uint4*)hv;
}

// ---------------- gather64: fp16 in, fp32 out --------------------------------
__global__ __launch_bounds__(256) void gather64h_kernel(
    const __half* __restrict__ x, float* __restrict__ out) {
    int v = (blockIdx.x * blockDim.x + threadIdx.x) >> 5;
    int lane = threadIdx.x & 31;
    if (v >= NN) return;
    int row = g_rowptr[v];
    int end = g_rowptr[v + 1];
    float2 acc = make_float2(0.f, 0.f);
    for (int base = row; base < end; base += 32) {
        int n = min(32, end - base);
        int s = 0;
        if (lane < n) s = __ldg(&g_esrc[base + lane]);
        int k = 0;
        for (; k + 4 <= n; k += 4) {
            int s0 = __shfl_sync(0xffffffffu, s, k);
            int s1 = __shfl_sync(0xffffffffu, s, k + 1);
            int s2 = __shfl_sync(0xffffffffu, s, k + 2);
            int s3 = __shfl_sync(0xffffffffu, s, k + 3);
            __half2 a0 = __ldg((const __half2*)(x + (size_t)s0 * 64) + lane);
            __half2 a1 = __ldg((const __half2*)(x + (size_t)s1 * 64) + lane);
            __half2 a2 = __ldg((const __half2*)(x + (size_t)s2 * 64) + lane);
            __half2 a3 = __ldg((const __half2*)(x + (size_t)s3 * 64) + lane);
            float2 f0 = __half22float2(a0);
            float2 f1 = __half22float2(a1);
            float2 f2 = __half22float2(a2);
            float2 f3 = __half22float2(a3);
            acc.x += (f0.x + f1.x) + (f2.x + f3.x);
            acc.y += (f0.y + f1.y) + (f2.y + f3.y);
        }
        for (; k < n; k++) {
            int s0 = __shfl_sync(0xffffffffu, s, k);
            float2 f0 = __half22float2(__ldg((const __half2*)(x + (size_t)s0 * 64) + lane));
            acc.x += f0.x;
            acc.y += f0.y;
        }
    }
    float w = g_dnorm[v];
    ((float2*)(out + (size_t)v * 64))[lane] = make_float2(acc.x * w, acc.y * w);
}

// ---------------- fp16 tensor-core GEMM, BK=64 -------------------------------
template <int BN, bool RELU>
__global__ __launch_bounds__(256, 2) void gemm_h_kernel(
    const __half* __restrict__ A, const __half* __restrict__ Wh,
    const float* __restrict__ norm, __half* __restrict__ C, int M, int N) {
    constexpr int BM = 128, BK = 64;
    constexpr int WM = (BN == 128) ? 64 : 32;
    constexpr int FM = WM / 16;
    constexpr int BQ = (BN == 128) ? 4 : 2;
    __shared__ __half As[BM][BK + 8];
    __shared__ __half Bs[BK][BN + 8];
    __shared__ float  stage[8][16 * 24];

    const int t = threadIdx.x;
    const int warp = t >> 5;
    const int lane = t & 31;
    const int wm = (BN == 128) ? (warp >> 2) : (warp >> 1);
    const int wn = (BN == 128) ? (warp & 3) : (warp & 1);
    const int row0 = blockIdx.x * BM;
    const int col0 = blockIdx.y * BN;

    const int a_row = t >> 1;
    const int a_c0 = (t & 1) * 32;
    const bool a_ok = (row0 + a_row) < M;
    const float nrmf = a_ok ? __ldg(&norm[row0 + a_row]) : 0.f;
    const __half2 nrm2 = __float2half2_rn(nrmf);
    const __half* Aptr = A + (size_t)(row0 + a_row) * 256 + a_c0;

    const int b_row = t >> 2;
    const int b_c0 = (t & 3) * 8 * BQ;

    wmma::fragment<wmma::accumulator, 16, 16, 16, float> acc[FM][2];
#pragma unroll
    for (int i = 0; i < FM; i++)
#pragma unroll
        for (int j = 0; j < 2; j++) wmma::fill_fragment(acc[i][j], 0.f);

    uint4 ar[4], br[BQ];
#pragma unroll
    for (int q = 0; q < 4; q++) ar[q] = *(const uint4*)(Aptr + q * 8);
#pragma unroll
    for (int q = 0; q < BQ; q++)
        br[q] = *(const uint4*)&Wh[(size_t)b_row * N + col0 + b_c0 + q * 8];

    auto store_tiles = [&]() {
#pragma unroll
        for (int q = 0; q < 4; q++) {
            const __half2* p = (const __half2*)&ar[q];
            __half2* dstp = (__half2*)&As[a_row][a_c0 + q * 8];
#pragma unroll
            for (int j = 0; j < 4; j++) dstp[j] = __hmul2(p[j], nrm2);
        }
#pragma unroll
        for (int q = 0; q < BQ; q++)
            *(uint4*)&Bs[b_row][b_c0 + q * 8] = br[q];
    };

    store_tiles();
    __syncthreads();

    for (int k0 = 0; k0 < 256; k0 += BK) {
        const bool has_next = (k0 + BK) < 256;
        if (has_next) {
#pragma unroll
            for (int q = 0; q < 4; q++)
                ar[q] = *(const uint4*)(Aptr + k0 + BK + q * 8);
#pragma unroll
            for (int q = 0; q < BQ; q++)
                br[q] = *(const uint4*)&Wh[(size_t)(k0 + BK + b_row) * N + col0 + b_c0 + q * 8];
        }
#pragma unroll
        for (int kk = 0; kk < BK; kk += 16) {
            wmma::fragment<wmma::matrix_a, 16, 16, 16, __half, wmma::row_major> af[FM];
            wmma::fragment<wmma::matrix_b, 16, 16, 16, __half, wmma::row_major> bf[2];
#pragma unroll
            for (int i = 0; i < FM; i++)
                wmma::load_matrix_sync(af[i], &As[wm * WM + i * 16][kk], BK + 8);
#pragma unroll
            for (int j = 0; j < 2; j++)
                wmma::load_matrix_sync(bf[j], &Bs[kk][wn * 32 + j * 16], BN + 8);
#pragma unroll
            for (int i = 0; i < FM; i++)
#pragma unroll
                for (int j = 0; j < 2; j++)
                    wmma::mma_sync(acc[i][j], af[i], bf[j], acc[i][j]);
        }
        __syncthreads();
        if (has_next) {
            store_tiles();
            __syncthreads();
        }
    }

#pragma unroll
    for (int i = 0; i < FM; i++)
#pragma unroll
        for (int j = 0; j < 2; j++) {
            if (RELU) {
#pragma unroll
                for (int e = 0; e < acc[i][j].num_elements; e++)
                    acc[i][j].x[e] = fmaxf(acc[i][j].x[e], 0.f);
            }
            wmma::store_matrix_sync(&stage[warp][0], acc[i][j], 24,
                                    wmma::mem_row_major);
            __syncwarp();
            int r = lane >> 1;
            int ch = (lane & 1) * 8;
            const float* sp = &stage[warp][r * 24 + ch];
            __half2 hv[4];
#pragma unroll
            for (int q = 0; q < 4; q++)
                hv[q] = __floats2half2_rn(sp[q * 2], sp[q * 2 + 1]);
            __half* cp = C + (size_t)(row0 + wm * WM + i * 16 + r) * N +
                         col0 + wn * 32 + j * 16 + ch;
            *(uint4*)cp = *(const uint4*)hv;
            __syncwarp();
        }
}

// ---------------- launch -----------------------------------------------------
extern "C" void kernel_launch(void* const* d_in, const int* in_sizes, int n_in,
                              void* d_out, int out_size) {
    const float* feat = (const float*)d_in[0];
    const int* src = (const int*)d_in[1];
    const int* dst = (const int*)d_in[2];
    const float* W0 = (const float*)d_in[3];
    const float* W1 = (const float*)d_in[4];
    const float* W2 = (const float*)d_in[5];
    float* out = (float*)d_out;
    const int nE = in_sizes[1];

    __half *xh, *aggh, *hh, *xmh, *w0h, *w1h, *w2h;
    float *snorm, *dnorm;
    cudaGetSymbolAddress((void**)&xh, g_xh);
    cudaGetSymbolAddress((void**)&aggh, g_aggh);
    cudaGetSymbolAddress((void**)&hh, g_hh);
    cudaGetSymbolAddress((void**)&xmh, g_xmh);
    cudaGetSymbolAddress((void**)&w0h, g_w0h);
    cudaGetSymbolAddress((void**)&w1h, g_w1h);
    cudaGetSymbolAddress((void**)&w2h, g_w2h);
    cudaGetSymbolAddress((void**)&snorm, g_snorm);
    cudaGetSymbolAddress((void**)&dnorm, g_dnorm);

    const int T = 256;
    const int NB = (NN + SCAN_BS - 1) / SCAN_BS;      // 196
    const int gemm_rows = NN_PAD / 128;               // 782
    const int gather_blocks = (NN * 32 + T - 1) / T;  // 12500
    const int conv8 = NN * 256 / 8;
    const int nE4 = (nE + 3) / 4;

    // degrees + CSR build (norms fused into scan3)
    zero_init_kernel<<<(NN + T - 1) / T, T>>>();
    degree_kernel<<<(nE4 + T - 1) / T, T>>>(src, dst, nE);
    scan1_kernel<<<NB, SCAN_BS>>>();
    scan2_kernel<<<1, 256>>>(NB);
    scan3_kernel<<<NB, SCAN_BS>>>(nE);
    fillcsr_kernel<<<(nE4 + T - 1) / T, T>>>(src, dst, nE);

    // feat + weight conversion (fp32 -> fp16)
    convert_half_kernel<<<(conv8 + T - 1) / T, T>>>(feat, xh, conv8);
    convert_weights_kernel<<<(18432 + T - 1) / T, T>>>(W0, W1, W2);

    // layer 0: aggh = A^T (xh * snorm); hh = relu((aggh * dnorm) @ W0)
    gather256h_kernel<<<gather_blocks, T>>>(xh, aggh);
    gemm_h_kernel<128, true><<<dim3(gemm_rows, 2), T>>>(aggh, w0h, dnorm, hh, NN, 256);

    // layer 1
    gather256h_kernel<<<gather_blocks, T>>>(hh, aggh);
    gemm_h_kernel<128, true><<<dim3(gemm_rows, 2), T>>>(aggh, w1h, dnorm, hh, NN, 256);

    // layer 2: xmh = (hh * snorm) @ W2; out = dnorm * (A^T xmh)
    gemm_h_kernel<64, false><<<dim3(gemm_rows, 1), T>>>(hh, w2h, snorm, xmh, NN, 64);
    gather64h_kernel<<<gather_blocks, T>>>(xmh, out);
}

// round 14
// speedup vs baseline: 1.0398x; 1.0007x over previous
#include <cuda_runtime.h>
#include <cuda_fp16.h>
#include <mma.h>
#include <cstdint>

using namespace nvcuda;

#define NN 100000
#define NN_PAD 100096   // 782 * 128
#define MAXE 3300000
#define SCAN_BS 512

// ---------------- scratch (static device globals; zero-initialized) ---------
__device__ __align__(256) int    g_indeg[NN];
__device__ __align__(256) int    g_outdeg[NN];
__device__ __align__(256) int    g_fill[NN];
__device__ __align__(256) int    g_rowptr[NN + 1];
__device__ __align__(256) int    g_blocksums[256];
__device__ __align__(256) int    g_esrc[MAXE];
__device__ __align__(256) float  g_snorm[NN];
__device__ __align__(256) float  g_dnorm[NN];
__device__ __align__(256) __half g_xh[(size_t)NN_PAD * 256];    // feat fp16
__device__ __align__(256) __half g_aggh[(size_t)NN_PAD * 256];  // agg fp16
__device__ __align__(256) __half g_hh[(size_t)NN_PAD * 256];    // h fp16
__device__ __align__(256) __half g_xmh[(size_t)NN_PAD * 64];    // xm fp16
__device__ __align__(256) __half g_w0h[256 * 256];
__device__ __align__(256) __half g_w1h[256 * 256];
__device__ __align__(256) __half g_w2h[256 * 64];

// ---------------- cp.async helpers ------------------------------------------
__device__ __forceinline__ void cp_async16(void* smem_ptr, const void* gptr) {
    uint32_t saddr = (uint32_t)__cvta_generic_to_shared(smem_ptr);
    asm volatile("cp.async.cg.shared.global [%0], [%1], 16;"
                 :: "r"(saddr), "l"(gptr) : "memory");
}
__device__ __forceinline__ void cp_commit() {
    asm volatile("cp.async.commit_group;" ::: "memory");
}
template <int N>
__device__ __forceinline__ void cp_wait() {
    asm volatile("cp.async.wait_group %0;" :: "n"(N) : "memory");
}

// ---------------- degrees --------------------------------------------------
__global__ void zero_init_kernel() {
    int i = blockIdx.x * blockDim.x + threadIdx.x;
    if (i < NN) { g_indeg[i] = 0; g_outdeg[i] = 0; }
}

__global__ void degree_kernel(const int* __restrict__ src,
                              const int* __restrict__ dst, int nE) {
    int i = blockIdx.x * blockDim.x + threadIdx.x;
    int base = i * 4;
    if (base + 4 <= nE) {
        int4 s = *(const int4*)(src + base);
        int4 d = *(const int4*)(dst + base);
        atomicAdd(&g_outdeg[s.x], 1);
        atomicAdd(&g_outdeg[s.y], 1);
        atomicAdd(&g_outdeg[s.z], 1);
        atomicAdd(&g_outdeg[s.w], 1);
        atomicAdd(&g_indeg[d.x], 1);
        atomicAdd(&g_indeg[d.y], 1);
        atomicAdd(&g_indeg[d.z], 1);
        atomicAdd(&g_indeg[d.w], 1);
    } else {
        for (int e = base; e < nE; e++) {
            atomicAdd(&g_outdeg[src[e]], 1);
            atomicAdd(&g_indeg[dst[e]], 1);
        }
    }
}

// ---------------- CSR build (norms fused into scan3) -------------------------
__global__ void scan1_kernel() {
    __shared__ int sh[SCAN_BS];
    int i = blockIdx.x * SCAN_BS + threadIdx.x;
    int v = (i < NN) ? g_indeg[i] : 0;
    sh[threadIdx.x] = v;
    __syncthreads();
    for (int off = 1; off < SCAN_BS; off <<= 1) {
        int t = (threadIdx.x >= off) ? sh[threadIdx.x - off] : 0;
        __syncthreads();
        sh[threadIdx.x] += t;
        __syncthreads();
    }
    if (i < NN) g_rowptr[i] = sh[threadIdx.x] - v;
    if (threadIdx.x == SCAN_BS - 1) g_blocksums[blockIdx.x] = sh[threadIdx.x];
}

__global__ void scan2_kernel(int nb) {
    __shared__ int sh[256];
    int t = threadIdx.x;
    int v = (t < nb) ? g_blocksums[t] : 0;
    sh[t] = v;
    __syncthreads();
    for (int off = 1; off < 256; off <<= 1) {
        int u = (t >= off) ? sh[t - off] : 0;
        __syncthreads();
        sh[t] += u;
        __syncthreads();
    }
    if (t < nb) g_blocksums[t] = sh[t] - v;
}

__global__ void scan3_kernel(int nE) {
    int i = blockIdx.x * SCAN_BS + threadIdx.x;
    if (i < NN) {
        int rp = g_rowptr[i] + g_blocksums[blockIdx.x];
        g_rowptr[i] = rp;
        g_fill[i] = rp;
        g_snorm[i] = rsqrtf(fmaxf((float)g_outdeg[i], 1.f));
        g_dnorm[i] = rsqrtf(fmaxf((float)g_indeg[i], 1.f));
    }
    if (i == 0) g_rowptr[NN] = nE;
}

__global__ void fillcsr_kernel(const int* __restrict__ src,
                               const int* __restrict__ dst, int nE) {
    int i = blockIdx.x * blockDim.x + threadIdx.x;
    int base = i * 4;
    if (base + 4 <= nE) {
        int4 s = *(const int4*)(src + base);
        int4 d = *(const int4*)(dst + base);
        g_esrc[atomicAdd(&g_fill[d.x], 1)] = s.x;
        g_esrc[atomicAdd(&g_fill[d.y], 1)] = s.y;
        g_esrc[atomicAdd(&g_fill[d.z], 1)] = s.z;
        g_esrc[atomicAdd(&g_fill[d.w], 1)] = s.w;
    } else {
        for (int e = base; e < nE; e++)
            g_esrc[atomicAdd(&g_fill[dst[e]], 1)] = src[e];
    }
}

// ---------------- fp32 -> fp16 converts --------------------------------------
__global__ void convert_half_kernel(const float* __restrict__ in,
                                    __half* __restrict__ out, int n8) {
    int i = blockIdx.x * blockDim.x + threadIdx.x;
    if (i >= n8) return;
    float4 a = ((const float4*)in)[i * 2];
    float4 b = ((const float4*)in)[i * 2 + 1];
    __half2 h[4];
    h[0] = __floats2half2_rn(a.x, a.y);
    h[1] = __floats2half2_rn(a.z, a.w);
    h[2] = __floats2half2_rn(b.x, b.y);
    h[3] = __floats2half2_rn(b.z, b.w);
    ((uint4*)out)[i] = *(const uint4*)h;
}

__global__ void convert_weights_kernel(const float* __restrict__ W0,
                                       const float* __restrict__ W1,
                                       const float* __restrict__ W2) {
    int i = blockIdx.x * blockDim.x + threadIdx.x;
    const float* in;
    __half* out;
    int off;
    if (i < 8192) { in = W0; out = g_w0h; off = i; }
    else if (i < 16384) { in = W1; out = g_w1h; off = i - 8192; }
    else if (i < 18432) { in = W2; out = g_w2h; off = i - 16384; }
    else return;
    float4 a = ((const float4*)in)[off * 2];
    float4 b = ((const float4*)in)[off * 2 + 1];
    __half2 h[4];
    h[0] = __floats2half2_rn(a.x, a.y);
    h[1] = __floats2half2_rn(a.z, a.w);
    h[2] = __floats2half2_rn(b.x, b.y);
    h[3] = __floats2half2_rn(b.z, b.w);
    ((uint4*)out)[off] = *(const uint4*)h;
}

// ---------------- gather256: fp16 in, fp32 accum, fp16 out -------------------
__global__ __launch_bounds__(256) void gather256h_kernel(
    const __half* __restrict__ x, __half* __restrict__ out) {
    int v = (blockIdx.x * blockDim.x + threadIdx.x) >> 5;
    int lane = threadIdx.x & 31;
    if (v >= NN) return;
    int row = g_rowptr[v];
    int end = g_rowptr[v + 1];
    float acc[8] = {0.f, 0.f, 0.f, 0.f, 0.f, 0.f, 0.f, 0.f};

    for (int base = row; base < end; base += 32) {
        int n = min(32, end - base);
        int s = 0;
        float w = 0.f;
        if (lane < n) { s = __ldg(&g_esrc[base + lane]); w = __ldg(&g_snorm[s]); }
        int k = 0;
        for (; k + 4 <= n; k += 4) {
            int s0 = __shfl_sync(0xffffffffu, s, k);
            int s1 = __shfl_sync(0xffffffffu, s, k + 1);
            int s2 = __shfl_sync(0xffffffffu, s, k + 2);
            int s3 = __shfl_sync(0xffffffffu, s, k + 3);
            float w0 = __shfl_sync(0xffffffffu, w, k);
            float w1 = __shfl_sync(0xffffffffu, w, k + 1);
            float w2 = __shfl_sync(0xffffffffu, w, k + 2);
            float w3 = __shfl_sync(0xffffffffu, w, k + 3);
            uint4 u0 = __ldg((const uint4*)(x + (size_t)s0 * 256) + lane);
            uint4 u1 = __ldg((const uint4*)(x + (size_t)s1 * 256) + lane);
            uint4 u2 = __ldg((const uint4*)(x + (size_t)s2 * 256) + lane);
            uint4 u3 = __ldg((const uint4*)(x + (size_t)s3 * 256) + lane);
            const __half2* p0 = (const __half2*)&u0;
            const __half2* p1 = (const __half2*)&u1;
            const __half2* p2 = (const __half2*)&u2;
            const __half2* p3 = (const __half2*)&u3;
#pragma unroll
            for (int j = 0; j < 4; j++) {
                float2 f0 = __half22float2(p0[j]);
                float2 f1 = __half22float2(p1[j]);
                float2 f2 = __half22float2(p2[j]);
                float2 f3 = __half22float2(p3[j]);
                acc[j * 2 + 0] += (w0 * f0.x + w1 * f1.x) + (w2 * f2.x + w3 * f3.x);
                acc[j * 2 + 1] += (w0 * f0.y + w1 * f1.y) + (w2 * f2.y + w3 * f3.y);
            }
        }
        for (; k < n; k++) {
            int s0 = __shfl_sync(0xffffffffu, s, k);
            float w0 = __shfl_sync(0xffffffffu, w, k);
            uint4 u0 = __ldg((const uint4*)(x + (size_t)s0 * 256) + lane);
            const __half2* p0 = (const __half2*)&u0;
#pragma unroll
            for (int j = 0; j < 4; j++) {
                float2 f0 = __half22float2(p0[j]);
                acc[j * 2 + 0] += w0 * f0.x;
                acc[j * 2 + 1] += w0 * f0.y;
            }
        }
    }
    __half2 hv[4];
#pragma unroll
    for (int j = 0; j < 4; j++)
        hv[j] = __floats2half2_rn(acc[j * 2], acc[j * 2 + 1]);
    ((uint4*)(out + (size_t)v * 256))[lane] = *(const uint4*)hv;
}

// ---------------- gather64: fp16 in, fp32 out --------------------------------
__global__ __launch_bounds__(256) void gather64h_kernel(
    const __half* __restrict__ x, float* __restrict__ out) {
    int v = (blockIdx.x * blockDim.x + threadIdx.x) >> 5;
    int lane = threadIdx.x & 31;
    if (v >= NN) return;
    int row = g_rowptr[v];
    int end = g_rowptr[v + 1];
    float2 acc = make_float2(0.f, 0.f);
    for (int base = row; base < end; base += 32) {
        int n = min(32, end - base);
        int s = 0;
        if (lane < n) s = __ldg(&g_esrc[base + lane]);
        int k = 0;
        for (; k + 4 <= n; k += 4) {
            int s0 = __shfl_sync(0xffffffffu, s, k);
            int s1 = __shfl_sync(0xffffffffu, s, k + 1);
            int s2 = __shfl_sync(0xffffffffu, s, k + 2);
            int s3 = __shfl_sync(0xffffffffu, s, k + 3);
            __half2 a0 = __ldg((const __half2*)(x + (size_t)s0 * 64) + lane);
            __half2 a1 = __ldg((const __half2*)(x + (size_t)s1 * 64) + lane);
            __half2 a2 = __ldg((const __half2*)(x + (size_t)s2 * 64) + lane);
            __half2 a3 = __ldg((const __half2*)(x + (size_t)s3 * 64) + lane);
            float2 f0 = __half22float2(a0);
            float2 f1 = __half22float2(a1);
            float2 f2 = __half22float2(a2);
            float2 f3 = __half22float2(a3);
            acc.x += (f0.x + f1.x) + (f2.x + f3.x);
            acc.y += (f0.y + f1.y) + (f2.y + f3.y);
        }
        for (; k < n; k++) {
            int s0 = __shfl_sync(0xffffffffu, s, k);
            float2 f0 = __half22float2(__ldg((const __half2*)(x + (size_t)s0 * 64) + lane));
            acc.x += f0.x;
            acc.y += f0.y;
        }
    }
    float w = g_dnorm[v];
    ((float2*)(out + (size_t)v * 64))[lane] = make_float2(acc.x * w, acc.y * w);
}

// ---------------- fp16 GEMM: cp.async double-buffer, norm in epilogue --------
// C[i,:] = act( norm[i] * (A[i,:] @ W) ).  A,W,C fp16, accum fp32, K=256.
// BM=128, BK=64 (4 stages). BN=128: warp tile 64x32; BN=64: 32x32.
template <int BN, bool RELU>
__global__ __launch_bounds__(256, 2) void gemm_h_kernel(
    const __half* __restrict__ A, const __half* __restrict__ Wh,
    const float* __restrict__ norm, __half* __restrict__ C, int M, int N) {
    constexpr int BM = 128, BK = 64;
    constexpr int NS = 256 / BK;                // 4 k-stages
    constexpr int AST = BK + 8;                 // 72 halves (144B, 16B-mult)
    constexpr int BST = BN + 8;                 // 136/72 halves (16B-mult)
    constexpr int WM = (BN == 128) ? 64 : 32;
    constexpr int FM = WM / 16;
    constexpr int BQ = (BN == 128) ? 4 : 2;     // 16B chunks per thread (B tile)

    extern __shared__ char dsm[];
    __half* As = (__half*)dsm;                          // [2][BM][AST]
    __half* Bs = (__half*)(dsm + 2 * BM * AST * 2);     // [2][BK][BST]
    float* stage = (float*)(dsm + 2 * BM * AST * 2 + 2 * BK * BST * 2);  // [8][16*24]

    const int t = threadIdx.x;
    const int warp = t >> 5;
    const int lane = t & 31;
    const int wm = (BN == 128) ? (warp >> 2) : (warp >> 1);
    const int wn = (BN == 128) ? (warp & 3) : (warp & 1);
    const int row0 = blockIdx.x * BM;
    const int col0 = blockIdx.y * BN;

    // A tile load map: 128 rows x 64 halves = 1024 x 16B; thread t -> row t>>1,
    // 4 chunks at halves (t&1)*32 + q*8
    const int a_row = t >> 1;
    const int a_c0 = (t & 1) * 32;
    const __half* Aptr = A + (size_t)(row0 + a_row) * 256 + a_c0;

    // B tile load map: 64 rows x BN halves; thread t -> row t>>2,
    // BQ chunks at halves (t&3)*BQ*8 + q*8
    const int b_row = t >> 2;
    const int b_c0 = (t & 3) * BQ * 8;

    auto load_tile = [&](int kt, int buf) {
        __half* ad = As + buf * BM * AST + a_row * AST + a_c0;
        const __half* ag = Aptr + kt * BK;
#pragma unroll
        for (int q = 0; q < 4; q++) cp_async16(ad + q * 8, ag + q * 8);
        __half* bd = Bs + buf * BK * BST + b_row * BST + b_c0;
        const __half* bg = Wh + (size_t)(kt * BK + b_row) * N + col0 + b_c0;
#pragma unroll
        for (int q = 0; q < BQ; q++) cp_async16(bd + q * 8, bg + q * 8);
    };

    wmma::fragment<wmma::accumulator, 16, 16, 16, float> acc[FM][2];
#pragma unroll
    for (int i = 0; i < FM; i++)
#pragma unroll
        for (int j = 0; j < 2; j++) wmma::fill_fragment(acc[i][j], 0.f);

    load_tile(0, 0);
    cp_commit();

    for (int s = 0; s < NS; s++) {
        if (s + 1 < NS) {
            load_tile(s + 1, (s + 1) & 1);
            cp_commit();
            cp_wait<1>();   // tile s arrived
        } else {
            cp_wait<0>();
        }
        __syncthreads();

        const __half* Ab = As + (s & 1) * BM * AST;
        const __half* Bb = Bs + (s & 1) * BK * BST;
#pragma unroll
        for (int kk = 0; kk < BK; kk += 16) {
            wmma::fragment<wmma::matrix_a, 16, 16, 16, __half, wmma::row_major> af[FM];
            wmma::fragment<wmma::matrix_b, 16, 16, 16, __half, wmma::row_major> bf[2];
#pragma unroll
            for (int i = 0; i < FM; i++)
                wmma::load_matrix_sync(af[i], Ab + (wm * WM + i * 16) * AST + kk, AST);
#pragma unroll
            for (int j = 0; j < 2; j++)
                wmma::load_matrix_sync(bf[j], Bb + kk * BST + wn * 32 + j * 16, BST);
#pragma unroll
            for (int i = 0; i < FM; i++)
#pragma unroll
                for (int j = 0; j < 2; j++)
                    wmma::mma_sync(acc[i][j], af[i], bf[j], acc[i][j]);
        }
        __syncthreads();   // all warps done with buf (s&1) before it is refilled
    }

    // epilogue: norm * acc (fp32), relu, fp16 store via warp staging
    float* wstage = stage + warp * 16 * 24;
#pragma unroll
    for (int i = 0; i < FM; i++) {
        int r = lane >> 1;
        int gr = row0 + wm * WM + i * 16 + r;
        float nf = (gr < M) ? __ldg(&norm[gr]) : 0.f;
#pragma unroll
        for (int j = 0; j < 2; j++) {
            wmma::store_matrix_sync(wstage, acc[i][j], 24, wmma::mem_row_major);
            __syncwarp();
            int ch = (lane & 1) * 8;
            const float* sp = wstage + r * 24 + ch;
            __half2 hv[4];
#pragma unroll
            for (int q = 0; q < 4; q++) {
                float lo = sp[q * 2] * nf;
                float hi = sp[q * 2 + 1] * nf;
                if (RELU) { lo = fmaxf(lo, 0.f); hi = fmaxf(hi, 0.f); }
                hv[q] = __floats2half2_rn(lo, hi);
            }
            __half* cp = C + (size_t)gr * N + col0 + wn * 32 + j * 16 + ch;
            *(uint4*)cp = *(const uint4*)hv;
            __syncwarp();
        }
    }
}

// ---------------- launch -----------------------------------------------------
extern "C" void kernel_launch(void* const* d_in, const int* in_sizes, int n_in,
                              void* d_out, int out_size) {
    const float* feat = (const float*)d_in[0];
    const int* src = (const int*)d_in[1];
    const int* dst = (const int*)d_in[2];
    const float* W0 = (const float*)d_in[3];
    const float* W1 = (const float*)d_in[4];
    const float* W2 = (const float*)d_in[5];
    float* out = (float*)d_out;
    const int nE = in_sizes[1];

    __half *xh, *aggh, *hh, *xmh, *w0h, *w1h, *w2h;
    float *snorm, *dnorm;
    cudaGetSymbolAddress((void**)&xh, g_xh);
    cudaGetSymbolAddress((void**)&aggh, g_aggh);
    cudaGetSymbolAddress((void**)&hh, g_hh);
    cudaGetSymbolAddress((void**)&xmh, g_xmh);
    cudaGetSymbolAddress((void**)&w0h, g_w0h);
    cudaGetSymbolAddress((void**)&w1h, g_w1h);
    cudaGetSymbolAddress((void**)&w2h, g_w2h);
    cudaGetSymbolAddress((void**)&snorm, g_snorm);
    cudaGetSymbolAddress((void**)&dnorm, g_dnorm);

    const int T = 256;
    const int NB = (NN + SCAN_BS - 1) / SCAN_BS;      // 196
    const int gemm_rows = NN_PAD / 128;               // 782
    const int gather_blocks = (NN * 32 + T - 1) / T;  // 12500
    const int conv8 = NN * 256 / 8;
    const int nE4 = (nE + 3) / 4;

    // dynamic smem sizes (must match kernel layout)
    const int SMEM128 = 2 * 128 * 72 * 2 + 2 * 64 * 136 * 2 + 8 * 16 * 24 * 4;  // 83968
    const int SMEM64 = 2 * 128 * 72 * 2 + 2 * 64 * 72 * 2 + 8 * 16 * 24 * 4;    // 67584
    cudaFuncSetAttribute(gemm_h_kernel<128, true>,
                         cudaFuncAttributeMaxDynamicSharedMemorySize, SMEM128);
    cudaFuncSetAttribute(gemm_h_kernel<64, false>,
                         cudaFuncAttributeMaxDynamicSharedMemorySize, SMEM64);

    // degrees + CSR build (norms fused into scan3)
    zero_init_kernel<<<(NN + T - 1) / T, T>>>();
    degree_kernel<<<(nE4 + T - 1) / T, T>>>(src, dst, nE);
    scan1_kernel<<<NB, SCAN_BS>>>();
    scan2_kernel<<<1, 256>>>(NB);
    scan3_kernel<<<NB, SCAN_BS>>>(nE);
    fillcsr_kernel<<<(nE4 + T - 1) / T, T>>>(src, dst, nE);

    // feat + weight conversion (fp32 -> fp16)
    convert_half_kernel<<<(conv8 + T - 1) / T, T>>>(feat, xh, conv8);
    convert_weights_kernel<<<(18432 + T - 1) / T, T>>>(W0, W1, W2);

    // layer 0: aggh = A^T (xh * snorm); hh = relu(dnorm * (aggh @ W0))
    gather256h_kernel<<<gather_blocks, T>>>(xh, aggh);
    gemm_h_kernel<128, true><<<dim3(gemm_rows, 2), T, SMEM128>>>(
        aggh, w0h, dnorm, hh, NN, 256);

    // layer 1
    gather256h_kernel<<<gather_blocks, T>>>(hh, aggh);
    gemm_h_kernel<128, true><<<dim3(gemm_rows, 2), T, SMEM128>>>(
        aggh, w1h, dnorm, hh, NN, 256);

    // layer 2: xmh = snorm * (hh @ W2); out = dnorm * (A^T xmh)
    gemm_h_kernel<64, false><<<dim3(gemm_rows, 1), T, SMEM64>>>(
        hh, w2h, snorm, xmh, NN, 64);
    gather64h_kernel<<<gather_blocks, T>>>(xmh, out);
}

// round 16
// speedup vs baseline: 1.1475x; 1.1036x over previous
#include <cuda_runtime.h>
#include <cuda_fp16.h>
#include <mma.h>
#include <cstdint>

using namespace nvcuda;

#define NN 100000
#define NN_PAD 100096   // 782 * 128
#define MAXE 3300000
#define SCAN_BS 512

// ---------------- scratch (static device globals; zero-initialized) ---------
__device__ __align__(256) int    g_indeg[NN];
__device__ __align__(256) int    g_outdeg[NN];
__device__ __align__(256) int    g_fill[NN];
__device__ __align__(256) int    g_rowptr[NN + 1];
__device__ __align__(256) int    g_blocksums[256];
__device__ __align__(256) int    g_esrc[MAXE];
__device__ __align__(256) float  g_snorm[NN];
__device__ __align__(256) float  g_dnorm[NN];
__device__ __align__(256) float  g_dsnorm[NN];   // dnorm * snorm
__device__ __align__(256) __half g_xh[(size_t)NN_PAD * 256];    // snorm-scaled feat fp16
__device__ __align__(256) __half g_aggh[(size_t)NN_PAD * 256];  // agg fp16
__device__ __align__(256) __half g_hh[(size_t)NN_PAD * 256];    // h' = snorm*h fp16
__device__ __align__(256) __half g_xmh[(size_t)NN_PAD * 64];    // xm fp16
__device__ __align__(256) __half g_w0h[256 * 256];
__device__ __align__(256) __half g_w1h[256 * 256];
__device__ __align__(256) __half g_w2h[256 * 64];

// ---------------- cp.async helpers ------------------------------------------
__device__ __forceinline__ void cp_async16(void* smem_ptr, const void* gptr) {
    uint32_t saddr = (uint32_t)__cvta_generic_to_shared(smem_ptr);
    asm volatile("cp.async.cg.shared.global [%0], [%1], 16;"
                 :: "r"(saddr), "l"(gptr) : "memory");
}
__device__ __forceinline__ void cp_commit() {
    asm volatile("cp.async.commit_group;" ::: "memory");
}
template <int N>
__device__ __forceinline__ void cp_wait() {
    asm volatile("cp.async.wait_group %0;" :: "n"(N) : "memory");
}

// ---------------- degrees --------------------------------------------------
__global__ void zero_init_kernel() {
    int i = blockIdx.x * blockDim.x + threadIdx.x;
    if (i < NN) { g_indeg[i] = 0; g_outdeg[i] = 0; }
}

__global__ void degree_kernel(const int* __restrict__ src,
                              const int* __restrict__ dst, int nE) {
    int i = blockIdx.x * blockDim.x + threadIdx.x;
    int base = i * 4;
    if (base + 4 <= nE) {
        int4 s = *(const int4*)(src + base);
        int4 d = *(const int4*)(dst + base);
        atomicAdd(&g_outdeg[s.x], 1);
        atomicAdd(&g_outdeg[s.y], 1);
        atomicAdd(&g_outdeg[s.z], 1);
        atomicAdd(&g_outdeg[s.w], 1);
        atomicAdd(&g_indeg[d.x], 1);
        atomicAdd(&g_indeg[d.y], 1);
        atomicAdd(&g_indeg[d.z], 1);
        atomicAdd(&g_indeg[d.w], 1);
    } else {
        for (int e = base; e < nE; e++) {
            atomicAdd(&g_outdeg[src[e]], 1);
            atomicAdd(&g_indeg[dst[e]], 1);
        }
    }
}

// ---------------- CSR build (norms fused into scan3) -------------------------
__global__ void scan1_kernel() {
    __shared__ int sh[SCAN_BS];
    int i = blockIdx.x * SCAN_BS + threadIdx.x;
    int v = (i < NN) ? g_indeg[i] : 0;
    sh[threadIdx.x] = v;
    __syncthreads();
    for (int off = 1; off < SCAN_BS; off <<= 1) {
        int t = (threadIdx.x >= off) ? sh[threadIdx.x - off] : 0;
        __syncthreads();
        sh[threadIdx.x] += t;
        __syncthreads();
    }
    if (i < NN) g_rowptr[i] = sh[threadIdx.x] - v;
    if (threadIdx.x == SCAN_BS - 1) g_blocksums[blockIdx.x] = sh[threadIdx.x];
}

__global__ void scan2_kernel(int nb) {
    __shared__ int sh[256];
    int t = threadIdx.x;
    int v = (t < nb) ? g_blocksums[t] : 0;
    sh[t] = v;
    __syncthreads();
    for (int off = 1; off < 256; off <<= 1) {
        int u = (t >= off) ? sh[t - off] : 0;
        __syncthreads();
        sh[t] += u;
        __syncthreads();
    }
    if (t < nb) g_blocksums[t] = sh[t] - v;
}

__global__ void scan3_kernel(int nE) {
    int i = blockIdx.x * SCAN_BS + threadIdx.x;
    if (i < NN) {
        int rp = g_rowptr[i] + g_blocksums[blockIdx.x];
        g_rowptr[i] = rp;
        g_fill[i] = rp;
        float sn = rsqrtf(fmaxf((float)g_outdeg[i], 1.f));
        float dn = rsqrtf(fmaxf((float)g_indeg[i], 1.f));
        g_snorm[i] = sn;
        g_dnorm[i] = dn;
        g_dsnorm[i] = sn * dn;
    }
    if (i == 0) g_rowptr[NN] = nE;
}

__global__ void fillcsr_kernel(const int* __restrict__ src,
                               const int* __restrict__ dst, int nE) {
    int i = blockIdx.x * blockDim.x + threadIdx.x;
    int base = i * 4;
    if (base + 4 <= nE) {
        int4 s = *(const int4*)(src + base);
        int4 d = *(const int4*)(dst + base);
        g_esrc[atomicAdd(&g_fill[d.x], 1)] = s.x;
        g_esrc[atomicAdd(&g_fill[d.y], 1)] = s.y;
        g_esrc[atomicAdd(&g_fill[d.z], 1)] = s.z;
        g_esrc[atomicAdd(&g_fill[d.w], 1)] = s.w;
    } else {
        for (int e = base; e < nE; e++)
            g_esrc[atomicAdd(&g_fill[dst[e]], 1)] = src[e];
    }
}

// ---------------- feat convert: xh[i,:] = snorm[i] * feat[i,:] (fp16) --------
// one thread = 8 elements of one row
__global__ void convert_feat_kernel(const float* __restrict__ in,
                                    __half* __restrict__ out, int n8) {
    int i = blockIdx.x * blockDim.x + threadIdx.x;
    if (i >= n8) return;
    int row = i >> 5;                 // 256 feats / 8 = 32 chunks per row
    float sn = __ldg(&g_snorm[row]);
    float4 a = ((const float4*)in)[i * 2];
    float4 b = ((const float4*)in)[i * 2 + 1];
    __half2 h[4];
    h[0] = __floats2half2_rn(a.x * sn, a.y * sn);
    h[1] = __floats2half2_rn(a.z * sn, a.w * sn);
    h[2] = __floats2half2_rn(b.x * sn, b.y * sn);
    h[3] = __floats2half2_rn(b.z * sn, b.w * sn);
    ((uint4*)out)[i] = *(const uint4*)h;
}

__global__ void convert_weights_kernel(const float* __restrict__ W0,
                                       const float* __restrict__ W1,
                                       const float* __restrict__ W2) {
    int i = blockIdx.x * blockDim.x + threadIdx.x;
    const float* in;
    __half* out;
    int off;
    if (i < 8192) { in = W0; out = g_w0h; off = i; }
    else if (i < 16384) { in = W1; out = g_w1h; off = i - 8192; }
    else if (i < 18432) { in = W2; out = g_w2h; off = i - 16384; }
    else return;
    float4 a = ((const float4*)in)[off * 2];
    float4 b = ((const float4*)in)[off * 2 + 1];
    __half2 h[4];
    h[0] = __floats2half2_rn(a.x, a.y);
    h[1] = __floats2half2_rn(a.z, a.w);
    h[2] = __floats2half2_rn(b.x, b.y);
    h[3] = __floats2half2_rn(b.z, b.w);
    ((uint4*)out)[off] = *(const uint4*)h;
}

// ---------------- gather256: pure sum (src-norm pre-folded into input) -------
__global__ __launch_bounds__(256) void gather256h_kernel(
    const __half* __restrict__ x, __half* __restrict__ out) {
    int v = (blockIdx.x * blockDim.x + threadIdx.x) >> 5;
    int lane = threadIdx.x & 31;
    if (v >= NN) return;
    int row = g_rowptr[v];
    int end = g_rowptr[v + 1];
    float acc[8] = {0.f, 0.f, 0.f, 0.f, 0.f, 0.f, 0.f, 0.f};

    for (int base = row; base < end; base += 32) {
        int n = min(32, end - base);
        int s = 0;
        if (lane < n) s = __ldg(&g_esrc[base + lane]);
        int k = 0;
        for (; k + 4 <= n; k += 4) {
            int s0 = __shfl_sync(0xffffffffu, s, k);
            int s1 = __shfl_sync(0xffffffffu, s, k + 1);
            int s2 = __shfl_sync(0xffffffffu, s, k + 2);
            int s3 = __shfl_sync(0xffffffffu, s, k + 3);
            uint4 u0 = __ldg((const uint4*)(x + (size_t)s0 * 256) + lane);
            uint4 u1 = __ldg((const uint4*)(x + (size_t)s1 * 256) + lane);
            uint4 u2 = __ldg((const uint4*)(x + (size_t)s2 * 256) + lane);
            uint4 u3 = __ldg((const uint4*)(x + (size_t)s3 * 256) + lane);
            const __half2* p0 = (const __half2*)&u0;
            const __half2* p1 = (const __half2*)&u1;
            const __half2* p2 = (const __half2*)&u2;
            const __half2* p3 = (const __half2*)&u3;
#pragma unroll
            for (int j = 0; j < 4; j++) {
                float2 f0 = __half22float2(p0[j]);
                float2 f1 = __half22float2(p1[j]);
                float2 f2 = __half22float2(p2[j]);
                float2 f3 = __half22float2(p3[j]);
                acc[j * 2 + 0] += (f0.x + f1.x) + (f2.x + f3.x);
                acc[j * 2 + 1] += (f0.y + f1.y) + (f2.y + f3.y);
            }
        }
        for (; k < n; k++) {
            int s0 = __shfl_sync(0xffffffffu, s, k);
            uint4 u0 = __ldg((const uint4*)(x + (size_t)s0 * 256) + lane);
            const __half2* p0 = (const __half2*)&u0;
#pragma unroll
            for (int j = 0; j < 4; j++) {
                float2 f0 = __half22float2(p0[j]);
                acc[j * 2 + 0] += f0.x;
                acc[j * 2 + 1] += f0.y;
            }
        }
    }
    __half2 hv[4];
#pragma unroll
    for (int j = 0; j < 4; j++)
        hv[j] = __floats2half2_rn(acc[j * 2], acc[j * 2 + 1]);
    ((uint4*)(out + (size_t)v * 256))[lane] = *(const uint4*)hv;
}

// ---------------- gather64: fp16 in, fp32 out --------------------------------
__global__ __launch_bounds__(256) void gather64h_kernel(
    const __half* __restrict__ x, float* __restrict__ out) {
    int v = (blockIdx.x * blockDim.x + threadIdx.x) >> 5;
    int lane = threadIdx.x & 31;
    if (v >= NN) return;
    int row = g_rowptr[v];
    int end = g_rowptr[v + 1];
    float2 acc = make_float2(0.f, 0.f);
    for (int base = row; base < end; base += 32) {
        int n = min(32, end - base);
        int s = 0;
        if (lane < n) s = __ldg(&g_esrc[base + lane]);
        int k = 0;
        for (; k + 4 <= n; k += 4) {
            int s0 = __shfl_sync(0xffffffffu, s, k);
            int s1 = __shfl_sync(0xffffffffu, s, k + 1);
            int s2 = __shfl_sync(0xffffffffu, s, k + 2);
            int s3 = __shfl_sync(0xffffffffu, s, k + 3);
            __half2 a0 = __ldg((const __half2*)(x + (size_t)s0 * 64) + lane);
            __half2 a1 = __ldg((const __half2*)(x + (size_t)s1 * 64) + lane);
            __half2 a2 = __ldg((const __half2*)(x + (size_t)s2 * 64) + lane);
            __half2 a3 = __ldg((const __half2*)(x + (size_t)s3 * 64) + lane);
            float2 f0 = __half22float2(a0);
            float2 f1 = __half22float2(a1);
            float2 f2 = __half22float2(a2);
            float2 f3 = __half22float2(a3);
            acc.x += (f0.x + f1.x) + (f2.x + f3.x);
            acc.y += (f0.y + f1.y) + (f2.y + f3.y);
        }
        for (; k < n; k++) {
            int s0 = __shfl_sync(0xffffffffu, s, k);
            float2 f0 = __half22float2(__ldg((const __half2*)(x + (size_t)s0 * 64) + lane));
            acc.x += f0.x;
            acc.y += f0.y;
        }
    }
    float w = g_dnorm[v];
    ((float2*)(out + (size_t)v * 64))[lane] = make_float2(acc.x * w, acc.y * w);
}

// ---------------- fp16 GEMM: cp.async double-buffer, norm in epilogue --------
// HASNORM: C[i,:] = act( norm[i] * (A[i,:] @ W) ); else C = act(A @ W).
template <int BN, bool RELU, bool HASNORM>
__global__ __launch_bounds__(256, 2) void gemm_h_kernel(
    const __half* __restrict__ A, const __half* __restrict__ Wh,
    const float* __restrict__ norm, __half* __restrict__ C, int M, int N) {
    constexpr int BM = 128, BK = 64;
    constexpr int NS = 256 / BK;                // 4 k-stages
    constexpr int AST = BK + 8;
    constexpr int BST = BN + 8;
    constexpr int WM = (BN == 128) ? 64 : 32;
    constexpr int FM = WM / 16;
    constexpr int BQ = (BN == 128) ? 4 : 2;

    extern __shared__ char dsm[];
    __half* As = (__half*)dsm;                          // [2][BM][AST]
    __half* Bs = (__half*)(dsm + 2 * BM * AST * 2);     // [2][BK][BST]
    float* stage = (float*)(dsm + 2 * BM * AST * 2 + 2 * BK * BST * 2);

    const int t = threadIdx.x;
    const int warp = t >> 5;
    const int lane = t & 31;
    const int wm = (BN == 128) ? (warp >> 2) : (warp >> 1);
    const int wn = (BN == 128) ? (warp & 3) : (warp & 1);
    const int row0 = blockIdx.x * BM;
    const int col0 = blockIdx.y * BN;

    const int a_row = t >> 1;
    const int a_c0 = (t & 1) * 32;
    const __half* Aptr = A + (size_t)(row0 + a_row) * 256 + a_c0;

    const int b_row = t >> 2;
    const int b_c0 = (t & 3) * BQ * 8;

    auto load_tile = [&](int kt, int buf) {
        __half* ad = As + buf * BM * AST + a_row * AST + a_c0;
        const __half* ag = Aptr + kt * BK;
#pragma unroll
        for (int q = 0; q < 4; q++) cp_async16(ad + q * 8, ag + q * 8);
        __half* bd = Bs + buf * BK * BST + b_row * BST + b_c0;
        const __half* bg = Wh + (size_t)(kt * BK + b_row) * N + col0 + b_c0;
#pragma unroll
        for (int q = 0; q < BQ; q++) cp_async16(bd + q * 8, bg + q * 8);
    };

    wmma::fragment<wmma::accumulator, 16, 16, 16, float> acc[FM][2];
#pragma unroll
    for (int i = 0; i < FM; i++)
#pragma unroll
        for (int j = 0; j < 2; j++) wmma::fill_fragment(acc[i][j], 0.f);

    load_tile(0, 0);
    cp_commit();

    for (int s = 0; s < NS; s++) {
        if (s + 1 < NS) {
            load_tile(s + 1, (s + 1) & 1);
            cp_commit();
            cp_wait<1>();
        } else {
            cp_wait<0>();
        }
        __syncthreads();

        const __half* Ab = As + (s & 1) * BM * AST;
        const __half* Bb = Bs + (s & 1) * BK * BST;
#pragma unroll
        for (int kk = 0; kk < BK; kk += 16) {
            wmma::fragment<wmma::matrix_a, 16, 16, 16, __half, wmma::row_major> af[FM];
            wmma::fragment<wmma::matrix_b, 16, 16, 16, __half, wmma::row_major> bf[2];
#pragma unroll
            for (int i = 0; i < FM; i++)
                wmma::load_matrix_sync(af[i], Ab + (wm * WM + i * 16) * AST + kk, AST);
#pragma unroll
            for (int j = 0; j < 2; j++)
                wmma::load_matrix_sync(bf[j], Bb + kk * BST + wn * 32 + j * 16, BST);
#pragma unroll
            for (int i = 0; i < FM; i++)
#pragma unroll
                for (int j = 0; j < 2; j++)
                    wmma::mma_sync(acc[i][j], af[i], bf[j], acc[i][j]);
        }
        __syncthreads();
    }

    float* wstage = stage + warp * 16 * 24;
#pragma unroll
    for (int i = 0; i < FM; i++) {
        int r = lane >> 1;
        int gr = row0 + wm * WM + i * 16 + r;
        float nf = 1.f;
        if (HASNORM) nf = (gr < M) ? __ldg(&norm[gr]) : 0.f;
#pragma unroll
        for (int j = 0; j < 2; j++) {
            wmma::store_matrix_sync(wstage, acc[i][j], 24, wmma::mem_row_major);
            __syncwarp();
            int ch = (lane & 1) * 8;
            const float* sp = wstage + r * 24 + ch;
            __half2 hv[4];
#pragma unroll
            for (int q = 0; q < 4; q++) {
                float lo = sp[q * 2] * nf;
                float hi = sp[q * 2 + 1] * nf;
                if (RELU) { lo = fmaxf(lo, 0.f); hi = fmaxf(hi, 0.f); }
                hv[q] = __floats2half2_rn(lo, hi);
            }
            __half* cp = C + (size_t)gr * N + col0 + wn * 32 + j * 16 + ch;
            *(uint4*)cp = *(const uint4*)hv;
            __syncwarp();
        }
    }
}

// ---------------- launch -----------------------------------------------------
extern "C" void kernel_launch(void* const* d_in, const int* in_sizes, int n_in,
                              void* d_out, int out_size) {
    const float* feat = (const float*)d_in[0];
    const int* src = (const int*)d_in[1];
    const int* dst = (const int*)d_in[2];
    const float* W0 = (const float*)d_in[3];
    const float* W1 = (const float*)d_in[4];
    const float* W2 = (const float*)d_in[5];
    float* out = (float*)d_out;
    const int nE = in_sizes[1];

    __half *xh, *aggh, *hh, *xmh, *w0h, *w1h, *w2h;
    float *dsnorm;
    cudaGetSymbolAddress((void**)&xh, g_xh);
    cudaGetSymbolAddress((void**)&aggh, g_aggh);
    cudaGetSymbolAddress((void**)&hh, g_hh);
    cudaGetSymbolAddress((void**)&xmh, g_xmh);
    cudaGetSymbolAddress((void**)&w0h, g_w0h);
    cudaGetSymbolAddress((void**)&w1h, g_w1h);
    cudaGetSymbolAddress((void**)&w2h, g_w2h);
    cudaGetSymbolAddress((void**)&dsnorm, g_dsnorm);

    const int T = 256;
    const int NB = (NN + SCAN_BS - 1) / SCAN_BS;      // 196
    const int gemm_rows = NN_PAD / 128;               // 782
    const int gather_blocks = (NN * 32 + T - 1) / T;  // 12500
    const int conv8 = NN * 256 / 8;
    const int nE4 = (nE + 3) / 4;

    const int SMEM128 = 2 * 128 * 72 * 2 + 2 * 64 * 136 * 2 + 8 * 16 * 24 * 4;
    const int SMEM64 = 2 * 128 * 72 * 2 + 2 * 64 * 72 * 2 + 8 * 16 * 24 * 4;
    cudaFuncSetAttribute(gemm_h_kernel<128, true, true>,
                         cudaFuncAttributeMaxDynamicSharedMemorySize, SMEM128);
    cudaFuncSetAttribute(gemm_h_kernel<64, false, false>,
                         cudaFuncAttributeMaxDynamicSharedMemorySize, SMEM64);

    // degrees + CSR build (norms + dsnorm fused into scan3)
    zero_init_kernel<<<(NN + T - 1) / T, T>>>();
    degree_kernel<<<(nE4 + T - 1) / T, T>>>(src, dst, nE);
    scan1_kernel<<<NB, SCAN_BS>>>();
    scan2_kernel<<<1, 256>>>(NB);
    scan3_kernel<<<NB, SCAN_BS>>>(nE);
    fillcsr_kernel<<<(nE4 + T - 1) / T, T>>>(src, dst, nE);

    // feat (pre-scaled by snorm) + weight conversion (fp32 -> fp16)
    convert_feat_kernel<<<(conv8 + T - 1) / T, T>>>(feat, xh, conv8);
    convert_weights_kernel<<<(18432 + T - 1) / T, T>>>(W0, W1, W2);

    // layer 0: aggh = A^T xh;  hh = relu(dsnorm * (aggh @ W0))   [hh = snorm*h]
    gather256h_kernel<<<gather_blocks, T>>>(xh, aggh);
    gemm_h_kernel<128, true, true><<<dim3(gemm_rows, 2), T, SMEM128>>>(
        aggh, w0h, dsnorm, hh, NN, 256);

    // layer 1: same, output again snorm-scaled
    gather256h_kernel<<<gather_blocks, T>>>(hh, aggh);
    gemm_h_kernel<128, true, true><<<dim3(gemm_rows, 2), T, SMEM128>>>(
        aggh, w1h, dsnorm, hh, NN, 256);

    // layer 2: xmh = hh @ W2 (snorm already folded); out = dnorm * (A^T xmh)
    gemm_h_kernel<64, false, false><<<dim3(gemm_rows, 1), T, SMEM64>>>(
        hh, w2h, nullptr, xmh, NN, 64);
    gather64h_kernel<<<gather_blocks, T>>>(xmh, out);
}